// round 8
// baseline (speedup 1.0000x reference)
#include <cuda_runtime.h>

#define MEM_M 131072
#define E 512

typedef unsigned long long u64;

// ---- device scratch (no allocation allowed) ----
// key GEMV partials: [m][p][E], m: 0=w_key, 1=r_key, 2=erase ; p = 8 chunks
__device__ __align__(16) float g_kpart[3 * 8 * E];
__device__ __align__(16) float g_accA[E];             // sum sims_r * mem
__device__ __align__(16) float g_accB[E];             // sum sims_r * sims_w * mem
__device__ float g_S[2];                              // S_r, S_w

// ---- packed f32x2 helpers (sm_103a native FFMA2) ----
__device__ __forceinline__ u64 pk2(float lo, float hi) {
    u64 r; asm("mov.b64 %0, {%1, %2};" : "=l"(r) : "f"(lo), "f"(hi)); return r;
}
__device__ __forceinline__ float hadd2(u64 v) {
    float lo, hi; asm("mov.b64 {%0, %1}, %2;" : "=f"(lo), "=f"(hi) : "l"(v));
    return lo + hi;
}
__device__ __forceinline__ u64 fma2(u64 a, u64 b, u64 c) {
    u64 r; asm("fma.rn.f32x2 %0, %1, %2, %3;" : "=l"(r) : "l"(a), "l"(b), "l"(c));
    return r;
}

// ============================================================
// K1 k_prep: key GEMV partials (UNNORMALIZED keys are fine:
// 1/||key|| cancels in weight = sims/sum(sims)) + zero scratch.
// blocks 0..23: m = b>>3, chunk p = b&7 (64 rows each), 512 thr.
// block 24: zero g_accA/g_accB/g_S/out.
// ============================================================
__global__ void k_prep(const float* __restrict__ x,
                       const float* __restrict__ wkg,
                       const float* __restrict__ weg,
                       const float* __restrict__ rkg,
                       float* __restrict__ out) {
    const int b = blockIdx.x, j = threadIdx.x;
    if (b == 24) {
        g_accA[j] = 0.f;
        g_accB[j] = 0.f;
        out[j] = 0.f;
        if (j < 2) g_S[j] = 0.f;
        return;
    }
    const int m = b >> 3, p = b & 7;
    const float* W = (m == 0) ? wkg : ((m == 1) ? rkg : weg);
    __shared__ float sx[64];
    if (j < 64) sx[j] = x[p * 64 + j];
    __syncthreads();
    float acc = 0.f;
#pragma unroll 8
    for (int i = 0; i < 64; i++)
        acc += sx[i] * W[(p * 64 + i) * E + j];
    g_kpart[(m * 8 + p) * E + j] = acc;
}

// ============================================================
// K3 k_main: single pass over memory (256 MB). One warp per row.
// Prologue: reduce the 8 key partials (L2-resident) into shared,
// then distribute to per-lane packed registers.
// Heavy math in packed f32x2 (FFMA2).
// ============================================================
#define PROCESS_ROW(V) do {                                                     \
    u64 dr2 = 0ull, dw2 = 0ull, nn2 = 0ull;                                     \
    _Pragma("unroll")                                                           \
    for (int i = 0; i < 8; i++) {                                               \
        dr2 = fma2(V[i], kr[i], dr2);                                           \
        dw2 = fma2(V[i], kw[i], dw2);                                           \
        nn2 = fma2(V[i], V[i], nn2);                                            \
    }                                                                           \
    float dr = hadd2(dr2), dw = hadd2(dw2), nn = hadd2(nn2);                    \
    _Pragma("unroll")                                                           \
    for (int o = 16; o; o >>= 1) {                                              \
        dr += __shfl_xor_sync(0xffffffffu, dr, o);                              \
        dw += __shfl_xor_sync(0xffffffffu, dw, o);                              \
        nn += __shfl_xor_sync(0xffffffffu, nn, o);                              \
    }                                                                           \
    const float inv = rsqrtf(nn);                                               \
    const float sr = dr * inv;                                                  \
    const float sw = dw * inv;                                                  \
    const float srw = sr * sw;                                                  \
    const u64 sr2 = pk2(sr, sr), srw2 = pk2(srw, srw);                          \
    _Pragma("unroll")                                                           \
    for (int i = 0; i < 8; i++) {                                               \
        acA[i] = fma2(V[i], sr2, acA[i]);                                       \
        acB[i] = fma2(V[i], srw2, acB[i]);                                      \
    }                                                                           \
    Sr += sr; Sw += sw;                                                         \
} while (0)

__global__ void __launch_bounds__(256, 2) k_main(const float* __restrict__ mem) {
    __shared__ u64 shA[8][256];   // 16 KB
    __shared__ u64 shB[8][256];   // 16 KB
    __shared__ float skey[2 * E]; // [0..511] = r_key, [512..1023] = w_key
    __shared__ float sS[16];

    const int tid = threadIdx.x;
    const int w = tid >> 5, l = tid & 31;
    const int gw = blockIdx.x * 8 + w;
    const int nW = gridDim.x * 8;

    // ---- prologue: reduce key partials (8 each) from L2 ----
    {
        const int which = tid >> 7;           // 0 -> r_key (m=1), 1 -> w_key (m=0)
        const int col = tid & 127;            // float4 column
        const int m = which ? 0 : 1;
        const float4* kp4 = (const float4*)g_kpart;
        float4 s = make_float4(0, 0, 0, 0);
#pragma unroll
        for (int p = 0; p < 8; p++) {
            float4 v = kp4[(m * 8 + p) * 128 + col];
            s.x += v.x; s.y += v.y; s.z += v.z; s.w += v.w;
        }
        ((float4*)skey)[which * 128 + col] = s;
    }
    __syncthreads();

    u64 kr[8], kw[8];
    {
        const u64* rk = (const u64*)skey;
        const u64* wk = (const u64*)(skey + E);
#pragma unroll
        for (int q = 0; q < 4; q++) {
            kr[2 * q]     = rk[(q * 32 + l) * 2];
            kr[2 * q + 1] = rk[(q * 32 + l) * 2 + 1];
            kw[2 * q]     = wk[(q * 32 + l) * 2];
            kw[2 * q + 1] = wk[(q * 32 + l) * 2 + 1];
        }
    }

    u64 acA[8], acB[8];
#pragma unroll
    for (int i = 0; i < 8; i++) { acA[i] = 0ull; acB[i] = 0ull; }
    float Sr = 0.f, Sw = 0.f;

    const int iters = (MEM_M - 1 - gw) / nW + 1;
    const float4* ptr = (const float4*)mem + (size_t)gw * 128 + l;
    const size_t stride = (size_t)nW * 128;

    u64 v[8], p[8];
#pragma unroll
    for (int q = 0; q < 4; q++) {
        float4 t = __ldcs(ptr + q * 32);
        v[2 * q]     = ((u64*)&t)[0];
        v[2 * q + 1] = ((u64*)&t)[1];
    }

    for (int it = 1; it < iters; ++it) {
        ptr += stride;
#pragma unroll
        for (int q = 0; q < 4; q++) {
            float4 t = __ldcs(ptr + q * 32);
            p[2 * q]     = ((u64*)&t)[0];
            p[2 * q + 1] = ((u64*)&t)[1];
        }
        PROCESS_ROW(v);
#pragma unroll
        for (int i = 0; i < 8; i++) v[i] = p[i];
    }
    PROCESS_ROW(v);

    // per-warp accumulators -> shared slices (same packed layout)
#pragma unroll
    for (int q = 0; q < 4; q++) {
        shA[w][(q * 32 + l) * 2]     = acA[2 * q];
        shA[w][(q * 32 + l) * 2 + 1] = acA[2 * q + 1];
        shB[w][(q * 32 + l) * 2]     = acB[2 * q];
        shB[w][(q * 32 + l) * 2 + 1] = acB[2 * q + 1];
    }
    if (l == 0) { sS[w] = Sr; sS[8 + w] = Sw; }
    __syncthreads();

    const float* fA = (const float*)shA;
    const float* fB = (const float*)shB;
    for (int j = tid; j < E; j += 256) {
        float a = 0.f, b = 0.f;
#pragma unroll
        for (int k = 0; k < 8; k++) {
            a += fA[k * E + j];
            b += fB[k * E + j];
        }
        atomicAdd(&g_accA[j], a);
        atomicAdd(&g_accB[j], b);
    }
    if (tid == 0) {
        float r = 0.f, ww = 0.f;
#pragma unroll
        for (int k = 0; k < 8; k++) { r += sS[k]; ww += sS[8 + k]; }
        atomicAdd(&g_S[0], r);
        atomicAdd(&g_S[1], ww);
    }
}

// ============================================================
// k_out_top: rows 0..511 of the output GEMV (coef = x).
// Independent of k_main -> runs on a side stream, hidden under it.
// 64 blocks x 256 threads; block b: rows [8b, 8b+8).
// ============================================================
__global__ void k_out_top(const float* __restrict__ x,
                          const float* __restrict__ post,
                          float* __restrict__ out) {
    const int b = blockIdx.x, t = threadIdx.x;
    const int half = t >> 7, c4 = t & 127;
    const int r = b * 8 + half * 4;
    const float4* p4 = (const float4*)post;
    const size_t base = (size_t)r * 128 + c4;
    const float4 v0 = p4[base];
    const float4 v1 = p4[base + 128];
    const float4 v2 = p4[base + 256];
    const float4 v3 = p4[base + 384];
    const float4 c = ((const float4*)x)[r >> 2];

    float4 acc;
    acc.x = c.x * v0.x + c.y * v1.x + c.z * v2.x + c.w * v3.x;
    acc.y = c.x * v0.y + c.y * v1.y + c.z * v2.y + c.w * v3.y;
    acc.z = c.x * v0.z + c.y * v1.z + c.z * v2.z + c.w * v3.z;
    acc.w = c.x * v0.w + c.y * v1.w + c.z * v2.w + c.w * v3.w;

    atomicAdd(&out[4 * c4 + 0], acc.x);
    atomicAdd(&out[4 * c4 + 1], acc.y);
    atomicAdd(&out[4 * c4 + 2], acc.z);
    atomicAdd(&out[4 * c4 + 3], acc.w);
}

// ============================================================
// k_out_bot: rows 512..1023 (coef = r_vect from accA/accB/erase).
// erase partials reduced inline (8 float4 from L2).
// ============================================================
__global__ void k_out_bot(const float* __restrict__ post,
                          float* __restrict__ out) {
    const int b = blockIdx.x, t = threadIdx.x;
    const int half = t >> 7, c4 = t & 127;
    const int r = E + b * 8 + half * 4;
    const float4* p4 = (const float4*)post;
    const size_t base = (size_t)r * 128 + c4;
    const float4 v0 = p4[base];
    const float4 v1 = p4[base + 128];
    const float4 v2 = p4[base + 256];
    const float4 v3 = p4[base + 384];

    const int e4 = (r - E) >> 2;
    const float4 a  = ((const float4*)g_accA)[e4];
    const float4 bb = ((const float4*)g_accB)[e4];
    float4 er = make_float4(0, 0, 0, 0);
    const float4* kp4 = (const float4*)g_kpart;
#pragma unroll
    for (int p = 0; p < 8; p++) {
        float4 v = kp4[(16 + p) * 128 + e4];
        er.x += v.x; er.y += v.y; er.z += v.z; er.w += v.w;
    }
    const float invSr = __frcp_rn(g_S[0]);
    const float invSw = __frcp_rn(g_S[1]);
    float4 c;
    c.x = (a.x - er.x * bb.x * invSw) * invSr;
    c.y = (a.y - er.y * bb.y * invSw) * invSr;
    c.z = (a.z - er.z * bb.z * invSw) * invSr;
    c.w = (a.w - er.w * bb.w * invSw) * invSr;

    float4 acc;
    acc.x = c.x * v0.x + c.y * v1.x + c.z * v2.x + c.w * v3.x;
    acc.y = c.x * v0.y + c.y * v1.y + c.z * v2.y + c.w * v3.y;
    acc.z = c.x * v0.z + c.y * v1.z + c.z * v2.z + c.w * v3.z;
    acc.w = c.x * v0.w + c.y * v1.w + c.z * v2.w + c.w * v3.w;

    atomicAdd(&out[4 * c4 + 0], acc.x);
    atomicAdd(&out[4 * c4 + 1], acc.y);
    atomicAdd(&out[4 * c4 + 2], acc.z);
    atomicAdd(&out[4 * c4 + 3], acc.w);
}

// ============================================================
extern "C" void kernel_launch(void* const* d_in, const int* in_sizes, int n_in,
                              void* d_out, int out_size) {
    const float* x    = (const float*)d_in[0];
    const float* mem  = (const float*)d_in[1];
    const float* wkg  = (const float*)d_in[2];
    // d_in[3] = w_vect_gen: computed-but-unused in the reference (dead)
    const float* weg  = (const float*)d_in[4];
    const float* rkg  = (const float*)d_in[5];
    const float* post = (const float*)d_in[6];
    float* out = (float*)d_out;

    // side stream + events for fork-join overlap (created once; host-side
    // resources only, no device allocation)
    static cudaStream_t s2 = nullptr;
    static cudaEvent_t e1 = nullptr, e2 = nullptr;
    if (s2 == nullptr) {
        cudaStreamCreateWithFlags(&s2, cudaStreamNonBlocking);
        cudaEventCreateWithFlags(&e1, cudaEventDisableTiming);
        cudaEventCreateWithFlags(&e2, cudaEventDisableTiming);
    }

    k_prep<<<25, 512>>>(x, wkg, weg, rkg, out);
    cudaEventRecord(e1, 0);

    // fork: top half of output GEMV runs concurrently with k_main
    cudaStreamWaitEvent(s2, e1, 0);
    k_out_top<<<64, 256, 0, s2>>>(x, post, out);
    cudaEventRecord(e2, s2);

    k_main<<<296, 256>>>(mem);

    // join
    cudaStreamWaitEvent(0, e2, 0);
    k_out_bot<<<64, 256>>>(post, out);
}

// round 12
// speedup vs baseline: 1.0647x; 1.0647x over previous
#include <cuda_runtime.h>

#define MEM_M 131072
#define E 512
#define CHROWS 4
#define NCHUNK (MEM_M / CHROWS)

typedef unsigned long long u64;

// ---- device scratch (no allocation allowed) ----
// key GEMV partials: [m][p][E], m: 0=w_key, 1=r_key, 2=erase ; p = 8 chunks
__device__ __align__(16) float g_kpart[3 * 8 * E];
__device__ __align__(16) float g_accA[E];             // sum sims_r * mem
__device__ __align__(16) float g_accB[E];             // sum sims_r * sims_w * mem
__device__ float g_S[2];                              // S_r, S_w
__device__ unsigned g_next;                           // work-stealing counter

// ---- packed f32x2 helpers (sm_103a native FFMA2) ----
__device__ __forceinline__ u64 pk2(float lo, float hi) {
    u64 r; asm("mov.b64 %0, {%1, %2};" : "=l"(r) : "f"(lo), "f"(hi)); return r;
}
__device__ __forceinline__ float hadd2(u64 v) {
    float lo, hi; asm("mov.b64 {%0, %1}, %2;" : "=f"(lo), "=f"(hi) : "l"(v));
    return lo + hi;
}
__device__ __forceinline__ u64 fma2(u64 a, u64 b, u64 c) {
    u64 r; asm("fma.rn.f32x2 %0, %1, %2, %3;" : "=l"(r) : "l"(a), "l"(b), "l"(c));
    return r;
}

// ============================================================
// K1 k_prep: key GEMV partials (UNNORMALIZED keys: 1/||key||
// cancels in weight = sims/sum(sims)) + zero scratch/counter.
// blocks 0..23: m = b>>3, chunk p = b&7 (64 rows), 512 threads.
// block 24: zero g_accA/g_accB/g_S/g_next/out.
// ============================================================
__global__ void k_prep(const float* __restrict__ x,
                       const float* __restrict__ wkg,
                       const float* __restrict__ weg,
                       const float* __restrict__ rkg,
                       float* __restrict__ out) {
    const int b = blockIdx.x, j = threadIdx.x;
    if (b == 24) {
        g_accA[j] = 0.f;
        g_accB[j] = 0.f;
        out[j] = 0.f;
        if (j < 2) g_S[j] = 0.f;
        if (j == 0) g_next = 0u;
        return;
    }
    const int m = b >> 3, p = b & 7;
    const float* W = (m == 0) ? wkg : ((m == 1) ? rkg : weg);
    __shared__ float sx[64];
    if (j < 64) sx[j] = x[p * 64 + j];
    __syncthreads();
    float acc = 0.f;
#pragma unroll 8
    for (int i = 0; i < 64; i++)
        acc += sx[i] * W[(p * 64 + i) * E + j];
    g_kpart[(m * 8 + p) * E + j] = acc;
}

// ============================================================
// K2 k_main: single pass over memory (256 MB), work-stealing.
// One warp processes 4-row contiguous chunks grabbed from g_next.
// Prologue reduces key partials from L2 into shared -> registers.
// Heavy math in packed f32x2 (FFMA2).
// ============================================================
#define PROCESS_ROW(V) do {                                                     \
    u64 dr2 = 0ull, dw2 = 0ull, nn2 = 0ull;                                     \
    _Pragma("unroll")                                                           \
    for (int i = 0; i < 8; i++) {                                               \
        dr2 = fma2(V[i], kr[i], dr2);                                           \
        dw2 = fma2(V[i], kw[i], dw2);                                           \
        nn2 = fma2(V[i], V[i], nn2);                                            \
    }                                                                           \
    float dr = hadd2(dr2), dw = hadd2(dw2), nn = hadd2(nn2);                    \
    _Pragma("unroll")                                                           \
    for (int o = 16; o; o >>= 1) {                                              \
        dr += __shfl_xor_sync(0xffffffffu, dr, o);                              \
        dw += __shfl_xor_sync(0xffffffffu, dw, o);                              \
        nn += __shfl_xor_sync(0xffffffffu, nn, o);                              \
    }                                                                           \
    const float inv = rsqrtf(nn);                                               \
    const float sr = dr * inv;                                                  \
    const float sw = dw * inv;                                                  \
    const float srw = sr * sw;                                                  \
    const u64 sr2 = pk2(sr, sr), srw2 = pk2(srw, srw);                          \
    _Pragma("unroll")                                                           \
    for (int i = 0; i < 8; i++) {                                               \
        acA[i] = fma2(V[i], sr2, acA[i]);                                       \
        acB[i] = fma2(V[i], srw2, acB[i]);                                      \
    }                                                                           \
    Sr += sr; Sw += sw;                                                         \
} while (0)

#define LOAD_ROW(D, rowptr) do {                                                \
    _Pragma("unroll")                                                           \
    for (int q = 0; q < 4; q++) {                                               \
        float4 t = __ldcs((rowptr) + q * 32);                                   \
        D[2 * q]     = ((u64*)&t)[0];                                           \
        D[2 * q + 1] = ((u64*)&t)[1];                                           \
    }                                                                           \
} while (0)

__global__ void __launch_bounds__(256, 2) k_main(const float* __restrict__ mem) {
    __shared__ u64 shA[8][256];   // 16 KB
    __shared__ u64 shB[8][256];   // 16 KB
    __shared__ float skey[2 * E]; // [0..511] = r_key, [512..1023] = w_key
    __shared__ float sS[16];

    const int tid = threadIdx.x;
    const int w = tid >> 5, l = tid & 31;

    // ---- prologue: reduce key partials (8 each) from L2 ----
    {
        const int which = tid >> 7;           // 0 -> r_key (m=1), 1 -> w_key (m=0)
        const int col = tid & 127;            // float4 column
        const int m = which ? 0 : 1;
        const float4* kp4 = (const float4*)g_kpart;
        float4 s = make_float4(0, 0, 0, 0);
#pragma unroll
        for (int p = 0; p < 8; p++) {
            float4 v = kp4[(m * 8 + p) * 128 + col];
            s.x += v.x; s.y += v.y; s.z += v.z; s.w += v.w;
        }
        ((float4*)skey)[which * 128 + col] = s;
    }
    __syncthreads();

    u64 kr[8], kw[8];
    {
        const u64* rk = (const u64*)skey;
        const u64* wk = (const u64*)(skey + E);
#pragma unroll
        for (int q = 0; q < 4; q++) {
            kr[2 * q]     = rk[(q * 32 + l) * 2];
            kr[2 * q + 1] = rk[(q * 32 + l) * 2 + 1];
            kw[2 * q]     = wk[(q * 32 + l) * 2];
            kw[2 * q + 1] = wk[(q * 32 + l) * 2 + 1];
        }
    }

    u64 acA[8], acB[8];
#pragma unroll
    for (int i = 0; i < 8; i++) { acA[i] = 0ull; acB[i] = 0ull; }
    float Sr = 0.f, Sw = 0.f;

    // ---- work-stealing mainloop: 4-row contiguous chunks ----
    unsigned c0 = 0, c1 = 0;
    if (l == 0) c0 = atomicAdd(&g_next, 1u);
    c0 = __shfl_sync(0xffffffffu, c0, 0);
    if (l == 0) c1 = atomicAdd(&g_next, 1u);
    c1 = __shfl_sync(0xffffffffu, c1, 0);

    u64 v[8], p[8];

    while (c0 < NCHUNK) {
        const float4* base = (const float4*)mem + (size_t)c0 * CHROWS * 128 + l;
        LOAD_ROW(v, base);
#pragma unroll
        for (int r = 0; r < CHROWS; r++) {
            // prefetch next row (next in chunk, or first row of next chunk)
            if (r < CHROWS - 1) {
                LOAD_ROW(p, base + (r + 1) * 128);
            } else if (c1 < NCHUNK) {
                const float4* nb = (const float4*)mem + (size_t)c1 * CHROWS * 128 + l;
                LOAD_ROW(p, nb);
            }
            PROCESS_ROW(v);
#pragma unroll
            for (int i = 0; i < 8; i++) v[i] = p[i];
        }
        c0 = c1;
        if (l == 0) c1 = atomicAdd(&g_next, 1u);   // one chunk ahead
        c1 = __shfl_sync(0xffffffffu, c1, 0);
    }

    // per-warp accumulators -> shared slices (same packed layout)
#pragma unroll
    for (int q = 0; q < 4; q++) {
        shA[w][(q * 32 + l) * 2]     = acA[2 * q];
        shA[w][(q * 32 + l) * 2 + 1] = acA[2 * q + 1];
        shB[w][(q * 32 + l) * 2]     = acB[2 * q];
        shB[w][(q * 32 + l) * 2 + 1] = acB[2 * q + 1];
    }
    if (l == 0) { sS[w] = Sr; sS[8 + w] = Sw; }
    __syncthreads();

    const float* fA = (const float*)shA;
    const float* fB = (const float*)shB;
    for (int j = tid; j < E; j += 256) {
        float a = 0.f, b = 0.f;
#pragma unroll
        for (int k = 0; k < 8; k++) {
            a += fA[k * E + j];
            b += fB[k * E + j];
        }
        atomicAdd(&g_accA[j], a);
        atomicAdd(&g_accB[j], b);
    }
    if (tid == 0) {
        float r = 0.f, ww = 0.f;
#pragma unroll
        for (int k = 0; k < 8; k++) { r += sS[k]; ww += sS[8 + k]; }
        atomicAdd(&g_S[0], r);
        atomicAdd(&g_S[1], ww);
    }
}

// ============================================================
// K3 k_out: output GEMV (R2 shape: 256 thr, shared coefs,
// scalar coalesced loads), atomics into d_out (zeroed by prep).
// 128 blocks; block b handles rows [8b, 8b+8).
// ============================================================
__global__ void k_out(const float* __restrict__ x,
                      const float* __restrict__ post,
                      float* __restrict__ out) {
    __shared__ float sc[8];
    const int b = blockIdx.x, t = threadIdx.x;
    const int i0 = b * 8;
    if (t < 8) {
        const int i = i0 + t;
        float ci;
        if (i < E) {
            ci = x[i];
        } else {
            const int e = i - E;
            float er = 0.f;
#pragma unroll
            for (int p = 0; p < 8; p++) er += g_kpart[(16 + p) * E + e];
            ci = (g_accA[e] - er * g_accB[e] * __frcp_rn(g_S[1])) * __frcp_rn(g_S[0]);
        }
        sc[t] = ci;
    }
    __syncthreads();
#pragma unroll
    for (int jj = 0; jj < 2; jj++) {
        const int j = t + jj * 256;
        float acc = 0.f;
#pragma unroll
        for (int i = 0; i < 8; i++)
            acc += sc[i] * post[(i0 + i) * E + j];
        atomicAdd(&out[j], acc);
    }
}

// ============================================================
extern "C" void kernel_launch(void* const* d_in, const int* in_sizes, int n_in,
                              void* d_out, int out_size) {
    const float* x    = (const float*)d_in[0];
    const float* mem  = (const float*)d_in[1];
    const float* wkg  = (const float*)d_in[2];
    // d_in[3] = w_vect_gen: computed-but-unused in the reference (dead)
    const float* weg  = (const float*)d_in[4];
    const float* rkg  = (const float*)d_in[5];
    const float* post = (const float*)d_in[6];
    float* out = (float*)d_out;

    k_prep<<<25, 512>>>(x, wkg, weg, rkg, out);
    k_main<<<296, 256>>>(mem);
    k_out<<<128, 256>>>(x, post, out);
}